// round 3
// baseline (speedup 1.0000x reference)
#include <cuda_runtime.h>
#include <cstdint>

// ---------------------------------------------------------------------------
// ColorHistogramMatchingLoss  (B=8, C=3, 256x256, D_HIST=64)
//
// loss = mean_b sqrt(0.5 * sum_{ch,i,j} (sqrt(Hy/Ty) - sqrt(Hx/Tx))^2)
// H[b,ch,i,j] = sum_n i_y[n] * rbf(u[n],c_i) * rbf(v[n],c_j)
// rbf(d,c) = 1 / (1 + ((d-c)/0.02)^2),  centers = linspace(-3,3,64)
// ---------------------------------------------------------------------------

#define NPIX        65536          // 256*256
#define BATCH       8
#define NUNITS      48             // 2 imgs * 8 batch * 3 ch
#define SPLITS      32
#define PIX_SPLIT   2048           // NPIX / SPLITS
#define CHUNK       64
#define NCHUNK      32             // PIX_SPLIT / CHUNK

// scaled centers: t = u*50 - c_k*50 ;  c_k*50 = k*(300/63) - 150
#define CK_STEP     (300.0f / 63.0f)

// -------------------------------- scratch ----------------------------------
__device__ float4 g_pix [2 * BATCH * NPIX];        // (su, sv, iy, 0)  16 MB
__device__ float  g_part[NUNITS * SPLITS * 4096];  // per-split partial hists
__device__ float  g_hist[NUNITS * 4096];           // reduced hists
__device__ float  g_hb  [BATCH];                   // per-batch h_norm

// ------------------------------ kernel 1: prep -----------------------------
__global__ void prep_kernel(const float* __restrict__ x,
                            const float* __restrict__ y) {
    int idx = blockIdx.x * 256 + threadIdx.x;        // [0, 2*8*65536)
    int img = idx >> 19;
    int b   = (idx >> 16) & 7;
    int pix = idx & (NPIX - 1);
    const float* im = img ? y : x;
    int base = b * (3 * NPIX) + pix;

    float r  = im[base]            + 1e-6f;
    float g  = im[base + NPIX]     + 1e-6f;
    float bl = im[base + 2 * NPIX] + 1e-6f;

    float lr = __logf(r), lg = __logf(g), lb = __logf(bl);
    float su = (lr - lg) * 50.0f;                    // 50*ur
    float sv = (lr - lb) * 50.0f;                    // 50*vr
    float iy = sqrtf(fmaf(r, r, fmaf(g, g, bl * bl)));

    g_pix[idx] = make_float4(su, sv, iy, 0.0f);
}

// ---------------------------- kernel 2: histogram --------------------------
// Block: 128 threads = 2 GEMM groups of 64.  Each group thread owns an 8x8
// tile of the 64x64 histogram as f32x2 accumulators (lanes = pixel parity).

#define FMA2(d, a, b) \
    asm("fma.rn.f32x2 %0, %1, %2, %0;" : "+l"(d) : "l"(a), "l"(b))

__device__ __forceinline__ float pair_sum(unsigned long long a) {
    return __uint_as_float((unsigned)a) + __uint_as_float((unsigned)(a >> 32));
}

__global__ __launch_bounds__(128) void hist_kernel() {
    // weight matrices, interleaved pixel-pair layout: [pp][k][parity]
    __shared__ __align__(16) float s_U[32 * 128];    // 16 KB (iy folded in)
    __shared__ __align__(16) float s_V[32 * 128];    // 16 KB
    __shared__ __align__(16) float4 s_pix[CHUNK];    // 1 KB

    const int tid   = threadIdx.x;
    const int bx    = blockIdx.x;
    const int split = bx & (SPLITS - 1);
    const int unit  = bx >> 5;                       // 0..47
    const int img   = unit / 24;
    const int rem   = unit - img * 24;
    const int b     = rem / 3;
    const int ch    = rem - b * 3;

    const float4* __restrict__ pix =
        g_pix + (img * BATCH + b) * NPIX + split * PIX_SPLIT;

    // (U,V) = linear combos of (su, sv) per channel:
    // ch0: U=su      V=sv        ch1: U=-su  V=sv-su     ch2: U=-sv  V=su-sv
    float ca, cb;
    if (tid < 64) {   // U producer
        ca = (ch == 0) ? 1.0f : (ch == 1) ? -1.0f : 0.0f;
        cb = (ch == 2) ? -1.0f : 0.0f;
    } else {          // V producer
        ca = (ch == 0) ? 0.0f : (ch == 1) ? -1.0f : 1.0f;
        cb = (ch == 2) ? -1.0f : 1.0f;
    }
    const int   khalf = tid & 63;
    const float ck    = khalf * CK_STEP - 150.0f;

    const int group = tid >> 6;                      // 0 / 1
    const int g     = tid & 63;
    const int r     = g >> 3;                        // row block (8 rows)
    const int c     = g & 7;                         // col block (8 cols)

    unsigned long long acc[8][8];
#pragma unroll
    for (int i = 0; i < 8; ++i)
#pragma unroll
        for (int j = 0; j < 8; ++j) acc[i][j] = 0ull;

    for (int chnk = 0; chnk < NCHUNK; ++chnk) {
        // ---- phase A0: stage 64 pixels ----
        if (tid < CHUNK) s_pix[tid] = pix[chnk * CHUNK + tid];
        __syncthreads();

        // ---- phase A1: generate weight matrices ----
        if (tid < 64) {
#pragma unroll 4
            for (int p = 0; p < CHUNK; ++p) {
                float4 px = s_pix[p];
                float d = fmaf(ca, px.x, cb * px.y) - ck;
                float q = fmaf(d, d, 1.0f);
                s_U[(p >> 1) * 128 + (khalf << 1) + (p & 1)] =
                    __fdividef(px.z, q);             // iy folded into U
            }
        } else {
#pragma unroll 4
            for (int p = 0; p < CHUNK; ++p) {
                float4 px = s_pix[p];
                float d = fmaf(ca, px.x, cb * px.y) - ck;
                float q = fmaf(d, d, 1.0f);
                s_V[(p >> 1) * 128 + (khalf << 1) + (p & 1)] =
                    __fdividef(1.0f, q);
            }
        }
        __syncthreads();

        // ---- phase B: rank-2 (pixel-pair) outer-product updates ----
        const float* sUb = s_U + r * 16;
        const float* sVb = s_V + c * 16;
#pragma unroll 2
        for (int q = 0; q < 16; ++q) {
            int pp = (group << 4) + q;
            const ulonglong2* pu =
                reinterpret_cast<const ulonglong2*>(sUb + pp * 128);
            const ulonglong2* pv =
                reinterpret_cast<const ulonglong2*>(sVb + pp * 128);
            ulonglong2 U0 = pu[0], U1 = pu[1], U2 = pu[2], U3 = pu[3];
            ulonglong2 V0 = pv[0], V1 = pv[1], V2 = pv[2], V3 = pv[3];
            unsigned long long u[8] = {U0.x, U0.y, U1.x, U1.y,
                                       U2.x, U2.y, U3.x, U3.y};
            unsigned long long v[8] = {V0.x, V0.y, V1.x, V1.y,
                                       V2.x, V2.y, V3.x, V3.y};
#pragma unroll
            for (int i = 0; i < 8; ++i)
#pragma unroll
                for (int j = 0; j < 8; ++j) FMA2(acc[i][j], u[i], v[j]);
        }
        __syncthreads();   // protect s_U/s_V before next A1 overwrites
    }

    // ---- combine both groups in smem, write partial histogram ----
    float* s_h = s_U;      // reuse as 64x64 hist buffer
    if (group == 0) {
#pragma unroll
        for (int i = 0; i < 8; ++i)
#pragma unroll
            for (int j = 0; j < 8; ++j)
                s_h[(r * 8 + i) * 64 + c * 8 + j] = pair_sum(acc[i][j]);
    }
    __syncthreads();
    if (group == 1) {
#pragma unroll
        for (int i = 0; i < 8; ++i)
#pragma unroll
            for (int j = 0; j < 8; ++j)
                s_h[(r * 8 + i) * 64 + c * 8 + j] += pair_sum(acc[i][j]);
    }
    __syncthreads();

    float* out = g_part + bx * 4096;
    for (int i = tid; i < 4096; i += 128) out[i] = s_h[i];
}

// ------------------------- kernel 3: reduce splits -------------------------
__global__ void reduce_splits_kernel() {
    int cid = blockIdx.x * 256 + threadIdx.x;        // < 48*4096
    int u   = cid >> 12;
    int cc  = cid & 4095;
    float s = 0.0f;
#pragma unroll 8
    for (int sp = 0; sp < SPLITS; ++sp)
        s += g_part[(u * SPLITS + sp) * 4096 + cc];
    g_hist[cid] = s;
}

// ------------------------- kernel 4: per-batch loss ------------------------
__device__ __forceinline__ float block_reduce(float v) {
    __shared__ float sb[8];
    int tid = threadIdx.x;
#pragma unroll
    for (int o = 16; o > 0; o >>= 1) v += __shfl_down_sync(0xffffffffu, v, o);
    if ((tid & 31) == 0) sb[tid >> 5] = v;
    __syncthreads();
    if (tid < 32) {
        v = (tid < 8) ? sb[tid] : 0.0f;
#pragma unroll
        for (int o = 4; o > 0; o >>= 1) v += __shfl_down_sync(0xffffffffu, v, o);
        if (tid == 0) sb[0] = v;
    }
    __syncthreads();
    v = sb[0];
    __syncthreads();
    return v;
}

__global__ void finalize_kernel() {
    const int b   = blockIdx.x;
    const int tid = threadIdx.x;
    const float* __restrict__ xh = g_hist + (b * 3) * 4096;        // img 0
    const float* __restrict__ yh = g_hist + (24 + b * 3) * 4096;   // img 1

    float tx = 0.0f, ty = 0.0f;
    for (int i = tid; i < 3 * 4096; i += 256) { tx += xh[i]; ty += yh[i]; }
    tx = block_reduce(tx);
    ty = block_reduce(ty);
    float sx = rsqrtf(tx), sy = rsqrtf(ty);

    float h = 0.0f;
    for (int i = tid; i < 3 * 4096; i += 256) {
        float d = sqrtf(yh[i]) * sy - sqrtf(xh[i]) * sx;
        h = fmaf(d, d, h);
    }
    h = block_reduce(h);
    if (tid == 0) g_hb[b] = sqrtf(h * 0.5f);
}

// --------------------------- kernel 5: final mean --------------------------
__global__ void mean_kernel(float* __restrict__ out) {
    if (threadIdx.x == 0) {
        float s = 0.0f;
#pragma unroll
        for (int i = 0; i < BATCH; ++i) s += g_hb[i];
        out[0] = s * (1.0f / BATCH);
    }
}

// ------------------------------- entry point -------------------------------
extern "C" void kernel_launch(void* const* d_in, const int* in_sizes, int n_in,
                              void* d_out, int out_size) {
    const float* x = (const float*)d_in[0];
    const float* y = (const float*)d_in[1];
    float* out = (float*)d_out;

    prep_kernel<<<(2 * BATCH * NPIX) / 256, 256>>>(x, y);
    hist_kernel<<<NUNITS * SPLITS, 128>>>();
    reduce_splits_kernel<<<(NUNITS * 4096) / 256, 256>>>();
    finalize_kernel<<<BATCH, 256>>>();
    mean_kernel<<<1, 32>>>(out);
}